// round 15
// baseline (speedup 1.0000x reference)
#include <cuda_runtime.h>
#include <cuda_bf16.h>
#include <cuda_fp16.h>
#include <math.h>
#include <stdint.h>
#include <cstdint>

#define NN 50000
#define NE 1600000
#define F0 512
#define F1 128
#define F2 40
#define NB_SCAN ((NN + 255) / 256)   // 196

// ---- scratch (static device globals; no allocation allowed) ----
__device__ int    g_is64;
__device__ int    g_src   [NE];
__device__ int    g_dst   [NE];
__device__ float  g_dinv[NN];
__device__ int    g_cnt   [NN];
__device__ int    g_off   [NN + 1];
__device__ int    g_cursor[NN];
__device__ int    g_bsum  [NB_SCAN];
__device__ int    g_bbase [NB_SCAN];
__device__ int    g_csr   [NE];
__device__ float  g_csrn  [NE];
__device__ __half g_h1h [(size_t)NN * F1];   // h1 fp16 (consumer: gather1)
__device__ float  g_agg1[(size_t)NN * F1];
__device__ __half g_h2h [(size_t)NN * F2];   // h2 fp16 (consumer: gather2)
// W1 transposed + bf16-split: [128 n][512 k]
__device__ __nv_bfloat16 g_w1t0[(size_t)F1 * F0];
__device__ __nv_bfloat16 g_w1t1[(size_t)F1 * F0];

__device__ __forceinline__ uint32_t smem_u32(const void* p) {
    uint32_t a;
    asm("{ .reg .u64 t; cvta.to.shared.u64 t, %1; cvt.u32.u64 %0, t; }"
        : "=r"(a) : "l"(p));
    return a;
}

#define LDMX4(r0, r1, r2, r3, addr) \
    asm volatile("ldmatrix.sync.aligned.m8n8.x4.shared.b16 {%0,%1,%2,%3}, [%4];" \
                 : "=r"(r0), "=r"(r1), "=r"(r2), "=r"(r3) : "r"(addr))

#define MMA_BF16(c, a, b) \
    asm volatile("mma.sync.aligned.m16n8k16.row.col.f32.bf16.bf16.f32 " \
                 "{%0,%1,%2,%3}, {%4,%5,%6,%7}, {%8,%9}, {%0,%1,%2,%3};" \
                 : "+f"((c)[0]), "+f"((c)[1]), "+f"((c)[2]), "+f"((c)[3]) \
                 : "r"((a)[0]), "r"((a)[1]), "r"((a)[2]), "r"((a)[3]), \
                   "r"((b)[0]), "r"((b)[1]))

// ---- init: zero counters + dtype detect + W1 transpose/split (merged) ----
__global__ void k_init(const unsigned int* __restrict__ raw,
                       const float* __restrict__ W1) {
    int i = blockIdx.x * blockDim.x + threadIdx.x;
    if (i < NN) g_cnt[i] = 0;
    if (i < F0 * F1) {
        int k = i / F1;
        int n = i - k * F1;
        float w = W1[i];
        __nv_bfloat16 b0 = __float2bfloat16_rn(w);
        float r = w - __bfloat162float(b0);
        __nv_bfloat16 b1 = __float2bfloat16_rn(r);
        g_w1t0[(size_t)n * F0 + k] = b0;
        g_w1t1[(size_t)n * F0 + k] = b1;
    }
    if (i == 0) {
        int is64 = 1;
        for (int j = 0; j < 64; j++)
            if (raw[2 * j + 1] != 0u) { is64 = 0; break; }
        g_is64 = is64;
    }
}

// ---- edge decode + degree count fused ----
__global__ void k_convert(const void* __restrict__ eiraw) {
    int i = blockIdx.x * blockDim.x + threadIdx.x;
    if (i >= 2 * NE) return;
    int v;
    if (g_is64) v = (int)((const long long*)eiraw)[i];
    else        v = ((const int*)eiraw)[i];
    if (i < NE) {
        g_src[i] = v;
    } else {
        g_dst[i - NE] = v;
        atomicAdd(&g_cnt[v], 1);
    }
}

__global__ void k_scanA() {
    __shared__ int s[256];
    int t = threadIdx.x;
    int i = blockIdx.x * 256 + t;
    int v = (i < NN) ? g_cnt[i] : 0;
    s[t] = v;
    __syncthreads();
    #pragma unroll
    for (int off = 1; off < 256; off <<= 1) {
        int u = (t >= off) ? s[t - off] : 0;
        __syncthreads();
        s[t] += u;
        __syncthreads();
    }
    if (i < NN) g_off[i] = s[t] - v;
    if (t == 255) g_bsum[blockIdx.x] = s[255];
}

__global__ void k_scanB() {
    __shared__ int s[256];
    int t = threadIdx.x;
    int v = (t < NB_SCAN) ? g_bsum[t] : 0;
    s[t] = v;
    __syncthreads();
    #pragma unroll
    for (int off = 1; off < 256; off <<= 1) {
        int u = (t >= off) ? s[t - off] : 0;
        __syncthreads();
        s[t] += u;
        __syncthreads();
    }
    if (t < NB_SCAN) g_bbase[t] = s[t] - v;
}

__global__ void k_scanC() {
    int i = blockIdx.x * blockDim.x + threadIdx.x;
    if (i < NN) {
        int val = g_off[i] + g_bbase[i >> 8];
        g_off[i]    = val;
        g_cursor[i] = val;
        g_dinv[i]   = rsqrtf((float)(g_cnt[i] + 1));
    }
    if (i == 0) g_off[NN] = NE;
}

__global__ void k_fill() {
    int e = blockIdx.x * blockDim.x + threadIdx.x;
    if (e >= NE) return;
    int s = g_src[e];
    int d = g_dst[e];
    int pos = atomicAdd(&g_cursor[d], 1);
    g_csr[pos]  = s;
    g_csrn[pos] = g_dinv[s] * g_dinv[d];
}

// ---- GEMM1 (mma.sync bf16x3, register-prefetch pipelined): h1 = x @ W1 ----
// BM=128, BN=128, BK=32, 8 warps (2 row x 4 col), warp tile 64x32.
#define SMPAD 40   // bf16 per smem row (32 data + 8 pad)

__global__ void __launch_bounds__(256) k_gemm1_mma(const float* __restrict__ A) {
    __shared__ __nv_bfloat16 sA0[128][SMPAD];
    __shared__ __nv_bfloat16 sA1[128][SMPAD];
    __shared__ __nv_bfloat16 sB0[128][SMPAD];
    __shared__ __nv_bfloat16 sB1[128][SMPAD];

    const int tid  = threadIdx.x;
    const int wid  = tid >> 5;
    const int lane = tid & 31;
    const int blockRow = blockIdx.x * 128;
    const int warpRowBase = (wid >> 2) * 64;
    const int warpColBase = (wid & 3) * 32;

    const int ldRow = tid >> 3;
    const int ldQ   = tid & 7;
    const bool aValid0 = (blockRow + ldRow +  0) < NN;
    const bool aValid1 = (blockRow + ldRow + 32) < NN;
    const bool aValid2 = (blockRow + ldRow + 64) < NN;
    const bool aValid3 = (blockRow + ldRow + 96) < NN;

    float acc[4][4][4];
    #pragma unroll
    for (int mt = 0; mt < 4; mt++)
        #pragma unroll
        for (int nt = 0; nt < 4; nt++)
            #pragma unroll
            for (int r = 0; r < 4; r++) acc[mt][nt][r] = 0.f;

    const uint32_t aOff = (uint32_t)(((warpRowBase + (lane & 15)) * SMPAD +
                                      (lane >> 4) * 8) * 2);
    const int grp = lane >> 3;
    const uint32_t bOff = (uint32_t)(((warpColBase + (grp >> 1) * 8 + (lane & 7)) * SMPAD +
                                      (grp & 1) * 8) * 2);

    const uint32_t a0b = smem_u32(&sA0[0][0]);
    const uint32_t a1b = smem_u32(&sA1[0][0]);
    const uint32_t b0b = smem_u32(&sB0[0][0]);
    const uint32_t b1b = smem_u32(&sB1[0][0]);

    float4 ra[4];
    uint2  rb0[4], rb1[4];

    // load chunk 0
    #pragma unroll
    for (int j = 0; j < 4; j++) {
        int row = ldRow + j * 32;
        bool ok = (j == 0) ? aValid0 : (j == 1) ? aValid1 : (j == 2) ? aValid2 : aValid3;
        ra[j] = ok ? *(const float4*)(A + (size_t)(blockRow + row) * F0 + ldQ * 4)
                   : make_float4(0.f, 0.f, 0.f, 0.f);
        rb0[j] = *(const uint2*)(g_w1t0 + (size_t)row * F0 + ldQ * 4);
        rb1[j] = *(const uint2*)(g_w1t1 + (size_t)row * F0 + ldQ * 4);
    }

    for (int chunk = 0; chunk < 16; chunk++) {
        #pragma unroll
        for (int j = 0; j < 4; j++) {
            int row = ldRow + j * 32;
            float4 v = ra[j];
            __nv_bfloat16 hx = __float2bfloat16_rn(v.x);
            __nv_bfloat16 hy = __float2bfloat16_rn(v.y);
            __nv_bfloat16 hz = __float2bfloat16_rn(v.z);
            __nv_bfloat16 hw = __float2bfloat16_rn(v.w);
            __nv_bfloat16 lx = __float2bfloat16_rn(v.x - __bfloat162float(hx));
            __nv_bfloat16 ly = __float2bfloat16_rn(v.y - __bfloat162float(hy));
            __nv_bfloat16 lz = __float2bfloat16_rn(v.z - __bfloat162float(hz));
            __nv_bfloat16 lw = __float2bfloat16_rn(v.w - __bfloat162float(hw));
            __nv_bfloat162 h01 = __halves2bfloat162(hx, hy);
            __nv_bfloat162 h23 = __halves2bfloat162(hz, hw);
            __nv_bfloat162 l01 = __halves2bfloat162(lx, ly);
            __nv_bfloat162 l23 = __halves2bfloat162(lz, lw);
            uint2 hv, lv;
            hv.x = *(uint32_t*)(&h01); hv.y = *(uint32_t*)(&h23);
            lv.x = *(uint32_t*)(&l01); lv.y = *(uint32_t*)(&l23);
            *(uint2*)(&sA0[row][ldQ * 4]) = hv;
            *(uint2*)(&sA1[row][ldQ * 4]) = lv;
            *(uint2*)(&sB0[row][ldQ * 4]) = rb0[j];
            *(uint2*)(&sB1[row][ldQ * 4]) = rb1[j];
        }
        __syncthreads();

        if (chunk < 15) {
            const int k0 = (chunk + 1) * 32;
            #pragma unroll
            for (int j = 0; j < 4; j++) {
                int row = ldRow + j * 32;
                bool ok = (j == 0) ? aValid0 : (j == 1) ? aValid1 : (j == 2) ? aValid2 : aValid3;
                ra[j] = ok ? *(const float4*)(A + (size_t)(blockRow + row) * F0 + k0 + ldQ * 4)
                           : make_float4(0.f, 0.f, 0.f, 0.f);
                rb0[j] = *(const uint2*)(g_w1t0 + (size_t)row * F0 + k0 + ldQ * 4);
                rb1[j] = *(const uint2*)(g_w1t1 + (size_t)row * F0 + k0 + ldQ * 4);
            }
        }

        #pragma unroll
        for (int ks = 0; ks < 2; ks++) {
            const uint32_t kb = ks * 32;
            uint32_t a0f[4][4], a1f[4][4];
            #pragma unroll
            for (int mt = 0; mt < 4; mt++) {
                uint32_t off = aOff + (uint32_t)(mt * 16 * SMPAD * 2) + kb;
                LDMX4(a0f[mt][0], a0f[mt][1], a0f[mt][2], a0f[mt][3], a0b + off);
                LDMX4(a1f[mt][0], a1f[mt][1], a1f[mt][2], a1f[mt][3], a1b + off);
            }
            uint32_t b0f[4][2], b1f[4][2];
            #pragma unroll
            for (int np = 0; np < 2; np++) {
                uint32_t off = bOff + (uint32_t)(np * 16 * SMPAD * 2) + kb;
                LDMX4(b0f[2*np][0], b0f[2*np][1], b0f[2*np+1][0], b0f[2*np+1][1],
                      b0b + off);
                LDMX4(b1f[2*np][0], b1f[2*np][1], b1f[2*np+1][0], b1f[2*np+1][1],
                      b1b + off);
            }
            #pragma unroll
            for (int mt = 0; mt < 4; mt++)
                #pragma unroll
                for (int nt = 0; nt < 4; nt++) {
                    MMA_BF16(acc[mt][nt], a0f[mt], b0f[nt]);
                    MMA_BF16(acc[mt][nt], a1f[mt], b0f[nt]);
                    MMA_BF16(acc[mt][nt], a0f[mt], b1f[nt]);
                }
        }
        __syncthreads();
    }

    // ---- epilogue: write h1 as fp16 ----
    #pragma unroll
    for (int mt = 0; mt < 4; mt++) {
        int r0 = blockRow + warpRowBase + mt * 16 + (lane >> 2);
        int r1 = r0 + 8;
        #pragma unroll
        for (int nt = 0; nt < 4; nt++) {
            int col = warpColBase + nt * 8 + 2 * (lane & 3);
            if (r0 < NN)
                *(__half2*)(g_h1h + (size_t)r0 * F1 + col) =
                    __floats2half2_rn(acc[mt][nt][0], acc[mt][nt][1]);
            if (r1 < NN)
                *(__half2*)(g_h1h + (size_t)r1 * F1 + col) =
                    __floats2half2_rn(acc[mt][nt][2], acc[mt][nt][3]);
        }
    }
}

// ---- gather layer 1: one warp per dst node, fp16 msgs, unroll x4 ----
__device__ __forceinline__ void acc_half4(float4& acc, const __half* p, float n) {
    uint2 u = *(const uint2*)p;
    __half2 p0 = *(__half2*)(&u.x);
    __half2 p1 = *(__half2*)(&u.y);
    float2 f0 = __half22float2(p0);
    float2 f1 = __half22float2(p1);
    acc.x += f0.x * n; acc.y += f0.y * n;
    acc.z += f1.x * n; acc.w += f1.y * n;
}

__global__ void k_gather1() {
    int g = blockIdx.x * blockDim.x + threadIdx.x;
    int node = g >> 5;
    int lane = g & 31;
    if (node >= NN) return;

    float dd = g_dinv[node];
    float4 acc = make_float4(0.f, 0.f, 0.f, 0.f);
    acc_half4(acc, g_h1h + (size_t)node * F1 + lane * 4, dd * dd);

    int beg = g_off[node];
    int end = g_off[node + 1];
    int j = beg;
    for (; j + 3 < end; j += 4) {
        int   s0 = __ldg(g_csr  + j + 0);
        int   s1 = __ldg(g_csr  + j + 1);
        int   s2 = __ldg(g_csr  + j + 2);
        int   s3 = __ldg(g_csr  + j + 3);
        float n0 = __ldg(g_csrn + j + 0);
        float n1 = __ldg(g_csrn + j + 1);
        float n2 = __ldg(g_csrn + j + 2);
        float n3 = __ldg(g_csrn + j + 3);
        acc_half4(acc, g_h1h + (size_t)s0 * F1 + lane * 4, n0);
        acc_half4(acc, g_h1h + (size_t)s1 * F1 + lane * 4, n1);
        acc_half4(acc, g_h1h + (size_t)s2 * F1 + lane * 4, n2);
        acc_half4(acc, g_h1h + (size_t)s3 * F1 + lane * 4, n3);
    }
    for (; j < end; j++) {
        int   s0 = __ldg(g_csr  + j);
        float n0 = __ldg(g_csrn + j);
        acc_half4(acc, g_h1h + (size_t)s0 * F1 + lane * 4, n0);
    }
    *(float4*)(g_agg1 + (size_t)node * F1 + lane * 4) = acc;
}

// ---- GEMM2: h2 = relu(agg1 + b1) @ W2, stored fp16 ----
__global__ void __launch_bounds__(128) k_gemm2(const float* __restrict__ W2,
                                               const float* __restrict__ b1) {
    __shared__ float sW[F1 * F2];
    __shared__ float sBias[F1];
    __shared__ float sA[64][65];

    const int tid = threadIdx.x;
    const int rowBase = blockIdx.x * 64;
    const int tx = tid & 7;
    const int ty = tid >> 3;

    for (int i = tid; i < F1 * F2; i += 128) sW[i] = W2[i];
    if (tid < F1) sBias[tid] = b1[tid];
    __syncthreads();

    float acc[4][5];
    #pragma unroll
    for (int j = 0; j < 4; j++)
        #pragma unroll
        for (int i = 0; i < 5; i++) acc[j][i] = 0.f;

    for (int kt = 0; kt < F1; kt += 64) {
        #pragma unroll
        for (int i = 0; i < 8; i++) {
            int f4  = tid + i * 128;
            int row = f4 >> 4;
            int c   = f4 & 15;
            int k   = kt + c * 4;
            int r   = rowBase + row;
            float4 v = make_float4(0.f, 0.f, 0.f, 0.f);
            if (r < NN)
                v = *(const float4*)(g_agg1 + (size_t)r * F1 + k);
            v.x = fmaxf(v.x + sBias[k + 0], 0.f);
            v.y = fmaxf(v.y + sBias[k + 1], 0.f);
            v.z = fmaxf(v.z + sBias[k + 2], 0.f);
            v.w = fmaxf(v.w + sBias[k + 3], 0.f);
            sA[row][c * 4 + 0] = v.x;
            sA[row][c * 4 + 1] = v.y;
            sA[row][c * 4 + 2] = v.z;
            sA[row][c * 4 + 3] = v.w;
        }
        __syncthreads();

        #pragma unroll 16
        for (int kk = 0; kk < 64; kk++) {
            float a[4], b[5];
            #pragma unroll
            for (int j = 0; j < 4; j++) a[j] = sA[ty * 4 + j][kk];
            #pragma unroll
            for (int i = 0; i < 5; i++) b[i] = sW[(kt + kk) * F2 + tx * 5 + i];
            #pragma unroll
            for (int j = 0; j < 4; j++)
                #pragma unroll
                for (int i = 0; i < 5; i++)
                    acc[j][i] += a[j] * b[i];
        }
        __syncthreads();
    }

    #pragma unroll
    for (int j = 0; j < 4; j++) {
        int r = rowBase + ty * 4 + j;
        if (r >= NN) continue;
        #pragma unroll
        for (int i = 0; i < 5; i++)
            g_h2h[(size_t)r * F2 + tx * 5 + i] = __float2half_rn(acc[j][i]);
    }
}

// ---- gather layer 2 + bias + log_softmax fused: one warp per node ----
__global__ void k_gather2_lsm(const float* __restrict__ b2,
                              float* __restrict__ out) {
    int g = blockIdx.x * blockDim.x + threadIdx.x;
    int node = g >> 5;
    int lane = g & 31;
    if (node >= NN) return;

    bool act = lane < 10;
    float dd = g_dinv[node];
    float4 acc = make_float4(0.f, 0.f, 0.f, 0.f);
    if (act)
        acc_half4(acc, g_h2h + (size_t)node * F2 + lane * 4, dd * dd);

    int beg = g_off[node];
    int end = g_off[node + 1];
    for (int j = beg; j < end; j++) {
        int   s    = __ldg(g_csr  + j);
        float norm = __ldg(g_csrn + j);
        if (act)
            acc_half4(acc, g_h2h + (size_t)s * F2 + lane * 4, norm);
    }

    if (act) {
        acc.x += b2[lane * 4 + 0];
        acc.y += b2[lane * 4 + 1];
        acc.z += b2[lane * 4 + 2];
        acc.w += b2[lane * 4 + 3];
    }

    float m = act ? fmaxf(fmaxf(acc.x, acc.y), fmaxf(acc.z, acc.w)) : -INFINITY;
    #pragma unroll
    for (int o = 16; o; o >>= 1) m = fmaxf(m, __shfl_xor_sync(0xFFFFFFFFu, m, o));
    float s = act ? (expf(acc.x - m) + expf(acc.y - m) +
                     expf(acc.z - m) + expf(acc.w - m)) : 0.f;
    #pragma unroll
    for (int o = 16; o; o >>= 1) s += __shfl_xor_sync(0xFFFFFFFFu, s, o);
    float l = m + logf(s);

    if (act) {
        float4 r = make_float4(acc.x - l, acc.y - l, acc.z - l, acc.w - l);
        *(float4*)(out + (size_t)node * F2 + lane * 4) = r;
    }
}

extern "C" void kernel_launch(void* const* d_in, const int* in_sizes, int n_in,
                              void* d_out, int out_size) {
    const float* x   = (const float*)d_in[0];
    const void*  ei  = d_in[1];
    const float* W1  = (const float*)d_in[2];
    const float* b1  = (const float*)d_in[3];
    const float* W2  = (const float*)d_in[4];
    const float* b2  = (const float*)d_in[5];
    float*       out = (float*)d_out;

    k_init    <<<(F0 * F1 + 255) / 256, 256>>>((const unsigned int*)ei, W1);
    k_convert <<<(2 * NE + 255) / 256, 256>>>(ei);
    k_scanA   <<<NB_SCAN, 256>>>();
    k_scanB   <<<1, 256>>>();
    k_scanC   <<<(NN + 255) / 256, 256>>>();
    k_fill    <<<(NE + 255) / 256, 256>>>();

    k_gemm1_mma<<<(NN + 127) / 128, 256>>>(x);
    k_gather1  <<<(int)(((long long)NN * 32 + 255) / 256), 256>>>();

    k_gemm2       <<<(NN + 63) / 64, 128>>>(W2, b1);
    k_gather2_lsm <<<(int)(((long long)NN * 32 + 255) / 256), 256>>>(b2, out);
}

// round 16
// speedup vs baseline: 1.0016x; 1.0016x over previous
#include <cuda_runtime.h>
#include <cuda_bf16.h>
#include <cuda_fp16.h>
#include <math.h>
#include <stdint.h>
#include <cstdint>

#define NN 50000
#define NE 1600000
#define F0 512
#define F1 128
#define F2 40
#define NB_SCAN ((NN + 255) / 256)   // 196

// ---- scratch (static device globals; no allocation allowed) ----
__device__ int    g_is64;
__device__ int    g_src   [NE];
__device__ int    g_dst   [NE];
__device__ float  g_dinv[NN];
__device__ int    g_cnt   [NN];
__device__ int    g_off   [NN + 1];
__device__ int    g_cursor[NN];
__device__ int    g_bsum  [NB_SCAN];
__device__ int    g_bbase [NB_SCAN];
__device__ int    g_csr   [NE];
__device__ float  g_csrn  [NE];
__device__ __half g_h1h [(size_t)NN * F1];   // h1 fp16 (consumer: gather1)
__device__ float  g_agg1[(size_t)NN * F1];
__device__ __half g_h2h [(size_t)NN * F2];   // h2 fp16 (consumer: gather2)
// W1 transposed + bf16-split: [128 n][512 k]
__device__ __nv_bfloat16 g_w1t0[(size_t)F1 * F0];
__device__ __nv_bfloat16 g_w1t1[(size_t)F1 * F0];

__device__ __forceinline__ uint32_t smem_u32(const void* p) {
    uint32_t a;
    asm("{ .reg .u64 t; cvta.to.shared.u64 t, %1; cvt.u32.u64 %0, t; }"
        : "=r"(a) : "l"(p));
    return a;
}

#define LDMX4(r0, r1, r2, r3, addr) \
    asm volatile("ldmatrix.sync.aligned.m8n8.x4.shared.b16 {%0,%1,%2,%3}, [%4];" \
                 : "=r"(r0), "=r"(r1), "=r"(r2), "=r"(r3) : "r"(addr))

#define MMA_BF16(c, a, b) \
    asm volatile("mma.sync.aligned.m16n8k16.row.col.f32.bf16.bf16.f32 " \
                 "{%0,%1,%2,%3}, {%4,%5,%6,%7}, {%8,%9}, {%0,%1,%2,%3};" \
                 : "+f"((c)[0]), "+f"((c)[1]), "+f"((c)[2]), "+f"((c)[3]) \
                 : "r"((a)[0]), "r"((a)[1]), "r"((a)[2]), "r"((a)[3]), \
                   "r"((b)[0]), "r"((b)[1]))

// ---- init: zero counters + dtype detect + W1 transpose/split (merged) ----
__global__ void k_init(const unsigned int* __restrict__ raw,
                       const float* __restrict__ W1) {
    int i = blockIdx.x * blockDim.x + threadIdx.x;
    if (i < NN) g_cnt[i] = 0;
    if (i < F0 * F1) {
        int k = i / F1;
        int n = i - k * F1;
        float w = W1[i];
        __nv_bfloat16 b0 = __float2bfloat16_rn(w);
        float r = w - __bfloat162float(b0);
        __nv_bfloat16 b1 = __float2bfloat16_rn(r);
        g_w1t0[(size_t)n * F0 + k] = b0;
        g_w1t1[(size_t)n * F0 + k] = b1;
    }
    if (i == 0) {
        int is64 = 1;
        for (int j = 0; j < 64; j++)
            if (raw[2 * j + 1] != 0u) { is64 = 0; break; }
        g_is64 = is64;
    }
}

// ---- edge decode + degree count fused ----
__global__ void k_convert(const void* __restrict__ eiraw) {
    int i = blockIdx.x * blockDim.x + threadIdx.x;
    if (i >= 2 * NE) return;
    int v;
    if (g_is64) v = (int)((const long long*)eiraw)[i];
    else        v = ((const int*)eiraw)[i];
    if (i < NE) {
        g_src[i] = v;
    } else {
        g_dst[i - NE] = v;
        atomicAdd(&g_cnt[v], 1);
    }
}

__global__ void k_scanA() {
    __shared__ int s[256];
    int t = threadIdx.x;
    int i = blockIdx.x * 256 + t;
    int v = (i < NN) ? g_cnt[i] : 0;
    s[t] = v;
    __syncthreads();
    #pragma unroll
    for (int off = 1; off < 256; off <<= 1) {
        int u = (t >= off) ? s[t - off] : 0;
        __syncthreads();
        s[t] += u;
        __syncthreads();
    }
    if (i < NN) g_off[i] = s[t] - v;
    if (t == 255) g_bsum[blockIdx.x] = s[255];
}

__global__ void k_scanB() {
    __shared__ int s[256];
    int t = threadIdx.x;
    int v = (t < NB_SCAN) ? g_bsum[t] : 0;
    s[t] = v;
    __syncthreads();
    #pragma unroll
    for (int off = 1; off < 256; off <<= 1) {
        int u = (t >= off) ? s[t - off] : 0;
        __syncthreads();
        s[t] += u;
        __syncthreads();
    }
    if (t < NB_SCAN) g_bbase[t] = s[t] - v;
}

__global__ void k_scanC() {
    int i = blockIdx.x * blockDim.x + threadIdx.x;
    if (i < NN) {
        int val = g_off[i] + g_bbase[i >> 8];
        g_off[i]    = val;
        g_cursor[i] = val;
        g_dinv[i]   = rsqrtf((float)(g_cnt[i] + 1));
    }
    if (i == 0) g_off[NN] = NE;
}

__global__ void k_fill() {
    int e = blockIdx.x * blockDim.x + threadIdx.x;
    if (e >= NE) return;
    int s = g_src[e];
    int d = g_dst[e];
    int pos = atomicAdd(&g_cursor[d], 1);
    g_csr[pos]  = s;
    g_csrn[pos] = g_dinv[s] * g_dinv[d];
}

// ---- GEMM1 (mma.sync bf16x3, register-prefetch pipelined): h1 = x @ W1 ----
// BM=128, BN=128, BK=32, 8 warps (2 row x 4 col), warp tile 64x32.
#define SMPAD 40   // bf16 per smem row (32 data + 8 pad)

__global__ void __launch_bounds__(256) k_gemm1_mma(const float* __restrict__ A) {
    __shared__ __nv_bfloat16 sA0[128][SMPAD];
    __shared__ __nv_bfloat16 sA1[128][SMPAD];
    __shared__ __nv_bfloat16 sB0[128][SMPAD];
    __shared__ __nv_bfloat16 sB1[128][SMPAD];

    const int tid  = threadIdx.x;
    const int wid  = tid >> 5;
    const int lane = tid & 31;
    const int blockRow = blockIdx.x * 128;
    const int warpRowBase = (wid >> 2) * 64;
    const int warpColBase = (wid & 3) * 32;

    const int ldRow = tid >> 3;
    const int ldQ   = tid & 7;
    const bool aValid0 = (blockRow + ldRow +  0) < NN;
    const bool aValid1 = (blockRow + ldRow + 32) < NN;
    const bool aValid2 = (blockRow + ldRow + 64) < NN;
    const bool aValid3 = (blockRow + ldRow + 96) < NN;

    float acc[4][4][4];
    #pragma unroll
    for (int mt = 0; mt < 4; mt++)
        #pragma unroll
        for (int nt = 0; nt < 4; nt++)
            #pragma unroll
            for (int r = 0; r < 4; r++) acc[mt][nt][r] = 0.f;

    const uint32_t aOff = (uint32_t)(((warpRowBase + (lane & 15)) * SMPAD +
                                      (lane >> 4) * 8) * 2);
    const int grp = lane >> 3;
    const uint32_t bOff = (uint32_t)(((warpColBase + (grp >> 1) * 8 + (lane & 7)) * SMPAD +
                                      (grp & 1) * 8) * 2);

    const uint32_t a0b = smem_u32(&sA0[0][0]);
    const uint32_t a1b = smem_u32(&sA1[0][0]);
    const uint32_t b0b = smem_u32(&sB0[0][0]);
    const uint32_t b1b = smem_u32(&sB1[0][0]);

    float4 ra[4];
    uint2  rb0[4], rb1[4];

    // load chunk 0
    #pragma unroll
    for (int j = 0; j < 4; j++) {
        int row = ldRow + j * 32;
        bool ok = (j == 0) ? aValid0 : (j == 1) ? aValid1 : (j == 2) ? aValid2 : aValid3;
        ra[j] = ok ? *(const float4*)(A + (size_t)(blockRow + row) * F0 + ldQ * 4)
                   : make_float4(0.f, 0.f, 0.f, 0.f);
        rb0[j] = *(const uint2*)(g_w1t0 + (size_t)row * F0 + ldQ * 4);
        rb1[j] = *(const uint2*)(g_w1t1 + (size_t)row * F0 + ldQ * 4);
    }

    for (int chunk = 0; chunk < 16; chunk++) {
        #pragma unroll
        for (int j = 0; j < 4; j++) {
            int row = ldRow + j * 32;
            float4 v = ra[j];
            __nv_bfloat16 hx = __float2bfloat16_rn(v.x);
            __nv_bfloat16 hy = __float2bfloat16_rn(v.y);
            __nv_bfloat16 hz = __float2bfloat16_rn(v.z);
            __nv_bfloat16 hw = __float2bfloat16_rn(v.w);
            __nv_bfloat16 lx = __float2bfloat16_rn(v.x - __bfloat162float(hx));
            __nv_bfloat16 ly = __float2bfloat16_rn(v.y - __bfloat162float(hy));
            __nv_bfloat16 lz = __float2bfloat16_rn(v.z - __bfloat162float(hz));
            __nv_bfloat16 lw = __float2bfloat16_rn(v.w - __bfloat162float(hw));
            __nv_bfloat162 h01 = __halves2bfloat162(hx, hy);
            __nv_bfloat162 h23 = __halves2bfloat162(hz, hw);
            __nv_bfloat162 l01 = __halves2bfloat162(lx, ly);
            __nv_bfloat162 l23 = __halves2bfloat162(lz, lw);
            uint2 hv, lv;
            hv.x = *(uint32_t*)(&h01); hv.y = *(uint32_t*)(&h23);
            lv.x = *(uint32_t*)(&l01); lv.y = *(uint32_t*)(&l23);
            *(uint2*)(&sA0[row][ldQ * 4]) = hv;
            *(uint2*)(&sA1[row][ldQ * 4]) = lv;
            *(uint2*)(&sB0[row][ldQ * 4]) = rb0[j];
            *(uint2*)(&sB1[row][ldQ * 4]) = rb1[j];
        }
        __syncthreads();

        if (chunk < 15) {
            const int k0 = (chunk + 1) * 32;
            #pragma unroll
            for (int j = 0; j < 4; j++) {
                int row = ldRow + j * 32;
                bool ok = (j == 0) ? aValid0 : (j == 1) ? aValid1 : (j == 2) ? aValid2 : aValid3;
                ra[j] = ok ? *(const float4*)(A + (size_t)(blockRow + row) * F0 + k0 + ldQ * 4)
                           : make_float4(0.f, 0.f, 0.f, 0.f);
                rb0[j] = *(const uint2*)(g_w1t0 + (size_t)row * F0 + k0 + ldQ * 4);
                rb1[j] = *(const uint2*)(g_w1t1 + (size_t)row * F0 + k0 + ldQ * 4);
            }
        }

        #pragma unroll
        for (int ks = 0; ks < 2; ks++) {
            const uint32_t kb = ks * 32;
            uint32_t a0f[4][4], a1f[4][4];
            #pragma unroll
            for (int mt = 0; mt < 4; mt++) {
                uint32_t off = aOff + (uint32_t)(mt * 16 * SMPAD * 2) + kb;
                LDMX4(a0f[mt][0], a0f[mt][1], a0f[mt][2], a0f[mt][3], a0b + off);
                LDMX4(a1f[mt][0], a1f[mt][1], a1f[mt][2], a1f[mt][3], a1b + off);
            }
            uint32_t b0f[4][2], b1f[4][2];
            #pragma unroll
            for (int np = 0; np < 2; np++) {
                uint32_t off = bOff + (uint32_t)(np * 16 * SMPAD * 2) + kb;
                LDMX4(b0f[2*np][0], b0f[2*np][1], b0f[2*np+1][0], b0f[2*np+1][1],
                      b0b + off);
                LDMX4(b1f[2*np][0], b1f[2*np][1], b1f[2*np+1][0], b1f[2*np+1][1],
                      b1b + off);
            }
            #pragma unroll
            for (int mt = 0; mt < 4; mt++)
                #pragma unroll
                for (int nt = 0; nt < 4; nt++) {
                    MMA_BF16(acc[mt][nt], a0f[mt], b0f[nt]);
                    MMA_BF16(acc[mt][nt], a1f[mt], b0f[nt]);
                    MMA_BF16(acc[mt][nt], a0f[mt], b1f[nt]);
                }
        }
        __syncthreads();
    }

    // ---- epilogue: write h1 as fp16 ----
    #pragma unroll
    for (int mt = 0; mt < 4; mt++) {
        int r0 = blockRow + warpRowBase + mt * 16 + (lane >> 2);
        int r1 = r0 + 8;
        #pragma unroll
        for (int nt = 0; nt < 4; nt++) {
            int col = warpColBase + nt * 8 + 2 * (lane & 3);
            if (r0 < NN)
                *(__half2*)(g_h1h + (size_t)r0 * F1 + col) =
                    __floats2half2_rn(acc[mt][nt][0], acc[mt][nt][1]);
            if (r1 < NN)
                *(__half2*)(g_h1h + (size_t)r1 * F1 + col) =
                    __floats2half2_rn(acc[mt][nt][2], acc[mt][nt][3]);
        }
    }
}

// ---- gather layer 1: one warp per dst node, fp16 msgs, unroll x4 ----
__device__ __forceinline__ void acc_half4(float4& acc, const __half* p, float n) {
    uint2 u = *(const uint2*)p;
    __half2 p0 = *(__half2*)(&u.x);
    __half2 p1 = *(__half2*)(&u.y);
    float2 f0 = __half22float2(p0);
    float2 f1 = __half22float2(p1);
    acc.x += f0.x * n; acc.y += f0.y * n;
    acc.z += f1.x * n; acc.w += f1.y * n;
}

__global__ void k_gather1() {
    int g = blockIdx.x * blockDim.x + threadIdx.x;
    int node = g >> 5;
    int lane = g & 31;
    if (node >= NN) return;

    float dd = g_dinv[node];
    float4 acc = make_float4(0.f, 0.f, 0.f, 0.f);
    acc_half4(acc, g_h1h + (size_t)node * F1 + lane * 4, dd * dd);

    int beg = g_off[node];
    int end = g_off[node + 1];
    int j = beg;
    for (; j + 3 < end; j += 4) {
        int   s0 = __ldg(g_csr  + j + 0);
        int   s1 = __ldg(g_csr  + j + 1);
        int   s2 = __ldg(g_csr  + j + 2);
        int   s3 = __ldg(g_csr  + j + 3);
        float n0 = __ldg(g_csrn + j + 0);
        float n1 = __ldg(g_csrn + j + 1);
        float n2 = __ldg(g_csrn + j + 2);
        float n3 = __ldg(g_csrn + j + 3);
        acc_half4(acc, g_h1h + (size_t)s0 * F1 + lane * 4, n0);
        acc_half4(acc, g_h1h + (size_t)s1 * F1 + lane * 4, n1);
        acc_half4(acc, g_h1h + (size_t)s2 * F1 + lane * 4, n2);
        acc_half4(acc, g_h1h + (size_t)s3 * F1 + lane * 4, n3);
    }
    for (; j < end; j++) {
        int   s0 = __ldg(g_csr  + j);
        float n0 = __ldg(g_csrn + j);
        acc_half4(acc, g_h1h + (size_t)s0 * F1 + lane * 4, n0);
    }
    *(float4*)(g_agg1 + (size_t)node * F1 + lane * 4) = acc;
}

// ---- GEMM2: h2 = relu(agg1 + b1) @ W2, stored fp16 ----
__global__ void __launch_bounds__(128) k_gemm2(const float* __restrict__ W2,
                                               const float* __restrict__ b1) {
    __shared__ float sW[F1 * F2];
    __shared__ float sBias[F1];
    __shared__ float sA[64][65];

    const int tid = threadIdx.x;
    const int rowBase = blockIdx.x * 64;
    const int tx = tid & 7;
    const int ty = tid >> 3;

    for (int i = tid; i < F1 * F2; i += 128) sW[i] = W2[i];
    if (tid < F1) sBias[tid] = b1[tid];
    __syncthreads();

    float acc[4][5];
    #pragma unroll
    for (int j = 0; j < 4; j++)
        #pragma unroll
        for (int i = 0; i < 5; i++) acc[j][i] = 0.f;

    for (int kt = 0; kt < F1; kt += 64) {
        #pragma unroll
        for (int i = 0; i < 8; i++) {
            int f4  = tid + i * 128;
            int row = f4 >> 4;
            int c   = f4 & 15;
            int k   = kt + c * 4;
            int r   = rowBase + row;
            float4 v = make_float4(0.f, 0.f, 0.f, 0.f);
            if (r < NN)
                v = *(const float4*)(g_agg1 + (size_t)r * F1 + k);
            v.x = fmaxf(v.x + sBias[k + 0], 0.f);
            v.y = fmaxf(v.y + sBias[k + 1], 0.f);
            v.z = fmaxf(v.z + sBias[k + 2], 0.f);
            v.w = fmaxf(v.w + sBias[k + 3], 0.f);
            sA[row][c * 4 + 0] = v.x;
            sA[row][c * 4 + 1] = v.y;
            sA[row][c * 4 + 2] = v.z;
            sA[row][c * 4 + 3] = v.w;
        }
        __syncthreads();

        #pragma unroll 16
        for (int kk = 0; kk < 64; kk++) {
            float a[4], b[5];
            #pragma unroll
            for (int j = 0; j < 4; j++) a[j] = sA[ty * 4 + j][kk];
            #pragma unroll
            for (int i = 0; i < 5; i++) b[i] = sW[(kt + kk) * F2 + tx * 5 + i];
            #pragma unroll
            for (int j = 0; j < 4; j++)
                #pragma unroll
                for (int i = 0; i < 5; i++)
                    acc[j][i] += a[j] * b[i];
        }
        __syncthreads();
    }

    #pragma unroll
    for (int j = 0; j < 4; j++) {
        int r = rowBase + ty * 4 + j;
        if (r >= NN) continue;
        #pragma unroll
        for (int i = 0; i < 5; i++)
            g_h2h[(size_t)r * F2 + tx * 5 + i] = __float2half_rn(acc[j][i]);
    }
}

// ---- gather layer 2 + bias + log_softmax fused: one warp per node ----
__global__ void k_gather2_lsm(const float* __restrict__ b2,
                              float* __restrict__ out) {
    int g = blockIdx.x * blockDim.x + threadIdx.x;
    int node = g >> 5;
    int lane = g & 31;
    if (node >= NN) return;

    bool act = lane < 10;
    float dd = g_dinv[node];
    float4 acc = make_float4(0.f, 0.f, 0.f, 0.f);
    if (act)
        acc_half4(acc, g_h2h + (size_t)node * F2 + lane * 4, dd * dd);

    int beg = g_off[node];
    int end = g_off[node + 1];
    for (int j = beg; j < end; j++) {
        int   s    = __ldg(g_csr  + j);
        float norm = __ldg(g_csrn + j);
        if (act)
            acc_half4(acc, g_h2h + (size_t)s * F2 + lane * 4, norm);
    }

    if (act) {
        acc.x += b2[lane * 4 + 0];
        acc.y += b2[lane * 4 + 1];
        acc.z += b2[lane * 4 + 2];
        acc.w += b2[lane * 4 + 3];
    }

    float m = act ? fmaxf(fmaxf(acc.x, acc.y), fmaxf(acc.z, acc.w)) : -INFINITY;
    #pragma unroll
    for (int o = 16; o; o >>= 1) m = fmaxf(m, __shfl_xor_sync(0xFFFFFFFFu, m, o));
    float s = act ? (expf(acc.x - m) + expf(acc.y - m) +
                     expf(acc.z - m) + expf(acc.w - m)) : 0.f;
    #pragma unroll
    for (int o = 16; o; o >>= 1) s += __shfl_xor_sync(0xFFFFFFFFu, s, o);
    float l = m + logf(s);

    if (act) {
        float4 r = make_float4(acc.x - l, acc.y - l, acc.z - l, acc.w - l);
        *(float4*)(out + (size_t)node * F2 + lane * 4) = r;
    }
}

extern "C" void kernel_launch(void* const* d_in, const int* in_sizes, int n_in,
                              void* d_out, int out_size) {
    const float* x   = (const float*)d_in[0];
    const void*  ei  = d_in[1];
    const float* W1  = (const float*)d_in[2];
    const float* b1  = (const float*)d_in[3];
    const float* W2  = (const float*)d_in[4];
    const float* b2  = (const float*)d_in[5];
    float*       out = (float*)d_out;

    k_init    <<<(F0 * F1 + 255) / 256, 256>>>((const unsigned int*)ei, W1);
    k_convert <<<(2 * NE + 255) / 256, 256>>>(ei);
    k_scanA   <<<NB_SCAN, 256>>>();
    k_scanB   <<<1, 256>>>();
    k_scanC   <<<(NN + 255) / 256, 256>>>();
    k_fill    <<<(NE + 255) / 256, 256>>>();

    k_gemm1_mma<<<(NN + 127) / 128, 256>>>(x);
    k_gather1  <<<(int)(((long long)NN * 32 + 255) / 256), 256>>>();

    k_gemm2       <<<(NN + 63) / 64, 128>>>(W2, b1);
    k_gather2_lsm <<<(int)(((long long)NN * 32 + 255) / 256), 256>>>(b2, out);
}

// round 17
// speedup vs baseline: 1.1665x; 1.1646x over previous
#include <cuda_runtime.h>
#include <cuda_fp16.h>
#include <math.h>
#include <stdint.h>
#include <cstdint>

#define NN 50000
#define NE 1600000
#define F0 512
#define F1 128
#define F2 40
#define NB_SCAN ((NN + 255) / 256)   // 196

// ---- scratch (static device globals; no allocation allowed) ----
__device__ int    g_is64;
__device__ int    g_src   [NE];
__device__ int    g_dst   [NE];
__device__ float  g_dinv[NN];
__device__ int    g_cnt   [NN];
__device__ int    g_off   [NN + 1];
__device__ int    g_cursor[NN];
__device__ int    g_bsum  [NB_SCAN];
__device__ int    g_bbase [NB_SCAN];
__device__ int2   g_csrp  [NE];              // packed (src, norm-bits)
__device__ __half g_h1h [(size_t)NN * F1];   // h1 fp16 (consumer: gather1)
__device__ float  g_agg1[(size_t)NN * F1];
__device__ __half g_h2h [(size_t)NN * F2];   // h2 fp16 (consumer: gather2)
__device__ __half g_w1h [(size_t)F1 * F0];   // W1 transposed fp16: [n][k]

__device__ __forceinline__ uint32_t smem_u32(const void* p) {
    uint32_t a;
    asm("{ .reg .u64 t; cvta.to.shared.u64 t, %1; cvt.u32.u64 %0, t; }"
        : "=r"(a) : "l"(p));
    return a;
}

#define LDMX4(r0, r1, r2, r3, addr) \
    asm volatile("ldmatrix.sync.aligned.m8n8.x4.shared.b16 {%0,%1,%2,%3}, [%4];" \
                 : "=r"(r0), "=r"(r1), "=r"(r2), "=r"(r3) : "r"(addr))

#define MMA_FP16(c, a, b) \
    asm volatile("mma.sync.aligned.m16n8k16.row.col.f32.f16.f16.f32 " \
                 "{%0,%1,%2,%3}, {%4,%5,%6,%7}, {%8,%9}, {%0,%1,%2,%3};" \
                 : "+f"((c)[0]), "+f"((c)[1]), "+f"((c)[2]), "+f"((c)[3]) \
                 : "r"((a)[0]), "r"((a)[1]), "r"((a)[2]), "r"((a)[3]), \
                   "r"((b)[0]), "r"((b)[1]))

// ---- init: zero counters + dtype detect + W1 transpose fp16 (merged) ----
__global__ void k_init(const unsigned int* __restrict__ raw,
                       const float* __restrict__ W1) {
    int i = blockIdx.x * blockDim.x + threadIdx.x;
    if (i < NN) g_cnt[i] = 0;
    if (i < F0 * F1) {
        int k = i / F1;
        int n = i - k * F1;
        g_w1h[(size_t)n * F0 + k] = __float2half_rn(W1[i]);
    }
    if (i == 0) {
        int is64 = 1;
        for (int j = 0; j < 64; j++)
            if (raw[2 * j + 1] != 0u) { is64 = 0; break; }
        g_is64 = is64;
    }
}

// ---- edge decode + degree count fused ----
__global__ void k_convert(const void* __restrict__ eiraw) {
    int i = blockIdx.x * blockDim.x + threadIdx.x;
    if (i >= 2 * NE) return;
    int v;
    if (g_is64) v = (int)((const long long*)eiraw)[i];
    else        v = ((const int*)eiraw)[i];
    if (i < NE) {
        g_src[i] = v;
    } else {
        g_dst[i - NE] = v;
        atomicAdd(&g_cnt[v], 1);
    }
}

__global__ void k_scanA() {
    __shared__ int s[256];
    int t = threadIdx.x;
    int i = blockIdx.x * 256 + t;
    int v = (i < NN) ? g_cnt[i] : 0;
    s[t] = v;
    __syncthreads();
    #pragma unroll
    for (int off = 1; off < 256; off <<= 1) {
        int u = (t >= off) ? s[t - off] : 0;
        __syncthreads();
        s[t] += u;
        __syncthreads();
    }
    if (i < NN) g_off[i] = s[t] - v;
    if (t == 255) g_bsum[blockIdx.x] = s[255];
}

__global__ void k_scanB() {
    __shared__ int s[256];
    int t = threadIdx.x;
    int v = (t < NB_SCAN) ? g_bsum[t] : 0;
    s[t] = v;
    __syncthreads();
    #pragma unroll
    for (int off = 1; off < 256; off <<= 1) {
        int u = (t >= off) ? s[t - off] : 0;
        __syncthreads();
        s[t] += u;
        __syncthreads();
    }
    if (t < NB_SCAN) g_bbase[t] = s[t] - v;
}

__global__ void k_scanC() {
    int i = blockIdx.x * blockDim.x + threadIdx.x;
    if (i < NN) {
        int val = g_off[i] + g_bbase[i >> 8];
        g_off[i]    = val;
        g_cursor[i] = val;
        g_dinv[i]   = rsqrtf((float)(g_cnt[i] + 1));
    }
    if (i == 0) g_off[NN] = NE;
}

__global__ void k_fill() {
    int e = blockIdx.x * blockDim.x + threadIdx.x;
    if (e >= NE) return;
    int s = g_src[e];
    int d = g_dst[e];
    int pos = atomicAdd(&g_cursor[d], 1);
    float nrm = g_dinv[s] * g_dinv[d];
    g_csrp[pos] = make_int2(s, __float_as_int(nrm));
}

// ---- GEMM1 (mma.sync fp16, register-prefetch pipelined): h1 = x @ W1 ----
// BM=128, BN=128, BK=32, 8 warps (2 row x 4 col), warp tile 64x32.
#define SMPAD 40   // fp16 per smem row (32 data + 8 pad)

__global__ void __launch_bounds__(256) k_gemm1_mma(const float* __restrict__ A) {
    __shared__ __half sA[128][SMPAD];
    __shared__ __half sB[128][SMPAD];

    const int tid  = threadIdx.x;
    const int wid  = tid >> 5;
    const int lane = tid & 31;
    const int blockRow = blockIdx.x * 128;
    const int warpRowBase = (wid >> 2) * 64;
    const int warpColBase = (wid & 3) * 32;

    const int ldRow = tid >> 3;
    const int ldQ   = tid & 7;
    const bool aValid0 = (blockRow + ldRow +  0) < NN;
    const bool aValid1 = (blockRow + ldRow + 32) < NN;
    const bool aValid2 = (blockRow + ldRow + 64) < NN;
    const bool aValid3 = (blockRow + ldRow + 96) < NN;

    float acc[4][4][4];
    #pragma unroll
    for (int mt = 0; mt < 4; mt++)
        #pragma unroll
        for (int nt = 0; nt < 4; nt++)
            #pragma unroll
            for (int r = 0; r < 4; r++) acc[mt][nt][r] = 0.f;

    const uint32_t aOff = (uint32_t)(((warpRowBase + (lane & 15)) * SMPAD +
                                      (lane >> 4) * 8) * 2);
    const int grp = lane >> 3;
    const uint32_t bOff = (uint32_t)(((warpColBase + (grp >> 1) * 8 + (lane & 7)) * SMPAD +
                                      (grp & 1) * 8) * 2);

    const uint32_t ab = smem_u32(&sA[0][0]);
    const uint32_t bb = smem_u32(&sB[0][0]);

    float4 ra[4];
    uint2  rb[4];

    // load chunk 0
    #pragma unroll
    for (int j = 0; j < 4; j++) {
        int row = ldRow + j * 32;
        bool ok = (j == 0) ? aValid0 : (j == 1) ? aValid1 : (j == 2) ? aValid2 : aValid3;
        ra[j] = ok ? *(const float4*)(A + (size_t)(blockRow + row) * F0 + ldQ * 4)
                   : make_float4(0.f, 0.f, 0.f, 0.f);
        rb[j] = *(const uint2*)(g_w1h + (size_t)row * F0 + ldQ * 4);
    }

    for (int chunk = 0; chunk < 16; chunk++) {
        #pragma unroll
        for (int j = 0; j < 4; j++) {
            int row = ldRow + j * 32;
            float4 v = ra[j];
            __half2 h01 = __floats2half2_rn(v.x, v.y);
            __half2 h23 = __floats2half2_rn(v.z, v.w);
            uint2 hv;
            hv.x = *(uint32_t*)(&h01); hv.y = *(uint32_t*)(&h23);
            *(uint2*)(&sA[row][ldQ * 4]) = hv;
            *(uint2*)(&sB[row][ldQ * 4]) = rb[j];
        }
        __syncthreads();

        if (chunk < 15) {
            const int k0 = (chunk + 1) * 32;
            #pragma unroll
            for (int j = 0; j < 4; j++) {
                int row = ldRow + j * 32;
                bool ok = (j == 0) ? aValid0 : (j == 1) ? aValid1 : (j == 2) ? aValid2 : aValid3;
                ra[j] = ok ? *(const float4*)(A + (size_t)(blockRow + row) * F0 + k0 + ldQ * 4)
                           : make_float4(0.f, 0.f, 0.f, 0.f);
                rb[j] = *(const uint2*)(g_w1h + (size_t)row * F0 + k0 + ldQ * 4);
            }
        }

        #pragma unroll
        for (int ks = 0; ks < 2; ks++) {
            const uint32_t kb = ks * 32;
            uint32_t af[4][4];
            #pragma unroll
            for (int mt = 0; mt < 4; mt++) {
                uint32_t off = aOff + (uint32_t)(mt * 16 * SMPAD * 2) + kb;
                LDMX4(af[mt][0], af[mt][1], af[mt][2], af[mt][3], ab + off);
            }
            uint32_t bf[4][2];
            #pragma unroll
            for (int np = 0; np < 2; np++) {
                uint32_t off = bOff + (uint32_t)(np * 16 * SMPAD * 2) + kb;
                LDMX4(bf[2*np][0], bf[2*np][1], bf[2*np+1][0], bf[2*np+1][1],
                      bb + off);
            }
            #pragma unroll
            for (int mt = 0; mt < 4; mt++)
                #pragma unroll
                for (int nt = 0; nt < 4; nt++)
                    MMA_FP16(acc[mt][nt], af[mt], bf[nt]);
        }
        __syncthreads();
    }

    // ---- epilogue: write h1 as fp16 ----
    #pragma unroll
    for (int mt = 0; mt < 4; mt++) {
        int r0 = blockRow + warpRowBase + mt * 16 + (lane >> 2);
        int r1 = r0 + 8;
        #pragma unroll
        for (int nt = 0; nt < 4; nt++) {
            int col = warpColBase + nt * 8 + 2 * (lane & 3);
            if (r0 < NN)
                *(__half2*)(g_h1h + (size_t)r0 * F1 + col) =
                    __floats2half2_rn(acc[mt][nt][0], acc[mt][nt][1]);
            if (r1 < NN)
                *(__half2*)(g_h1h + (size_t)r1 * F1 + col) =
                    __floats2half2_rn(acc[mt][nt][2], acc[mt][nt][3]);
        }
    }
}

// ---- gather layer 1: one warp per dst node, fp16 msgs, unroll x4 ----
__device__ __forceinline__ void acc_half4(float4& acc, const __half* p, float n) {
    uint2 u = *(const uint2*)p;
    __half2 p0 = *(__half2*)(&u.x);
    __half2 p1 = *(__half2*)(&u.y);
    float2 f0 = __half22float2(p0);
    float2 f1 = __half22float2(p1);
    acc.x += f0.x * n; acc.y += f0.y * n;
    acc.z += f1.x * n; acc.w += f1.y * n;
}

__global__ void k_gather1() {
    int g = blockIdx.x * blockDim.x + threadIdx.x;
    int node = g >> 5;
    int lane = g & 31;
    if (node >= NN) return;

    float dd = g_dinv[node];
    float4 acc = make_float4(0.f, 0.f, 0.f, 0.f);
    acc_half4(acc, g_h1h + (size_t)node * F1 + lane * 4, dd * dd);

    int beg = g_off[node];
    int end = g_off[node + 1];
    int j = beg;
    for (; j + 3 < end; j += 4) {
        int2 p0 = __ldg(g_csrp + j + 0);
        int2 p1 = __ldg(g_csrp + j + 1);
        int2 p2 = __ldg(g_csrp + j + 2);
        int2 p3 = __ldg(g_csrp + j + 3);
        acc_half4(acc, g_h1h + (size_t)p0.x * F1 + lane * 4, __int_as_float(p0.y));
        acc_half4(acc, g_h1h + (size_t)p1.x * F1 + lane * 4, __int_as_float(p1.y));
        acc_half4(acc, g_h1h + (size_t)p2.x * F1 + lane * 4, __int_as_float(p2.y));
        acc_half4(acc, g_h1h + (size_t)p3.x * F1 + lane * 4, __int_as_float(p3.y));
    }
    for (; j < end; j++) {
        int2 p0 = __ldg(g_csrp + j);
        acc_half4(acc, g_h1h + (size_t)p0.x * F1 + lane * 4, __int_as_float(p0.y));
    }
    *(float4*)(g_agg1 + (size_t)node * F1 + lane * 4) = acc;
}

// ---- GEMM2: h2 = relu(agg1 + b1) @ W2, stored fp16 ----
__global__ void __launch_bounds__(128) k_gemm2(const float* __restrict__ W2,
                                               const float* __restrict__ b1) {
    __shared__ float sW[F1 * F2];
    __shared__ float sBias[F1];
    __shared__ float sA[64][65];

    const int tid = threadIdx.x;
    const int rowBase = blockIdx.x * 64;
    const int tx = tid & 7;
    const int ty = tid >> 3;

    for (int i = tid; i < F1 * F2; i += 128) sW[i] = W2[i];
    if (tid < F1) sBias[tid] = b1[tid];
    __syncthreads();

    float acc[4][5];
    #pragma unroll
    for (int j = 0; j < 4; j++)
        #pragma unroll
        for (int i = 0; i < 5; i++) acc[j][i] = 0.f;

    for (int kt = 0; kt < F1; kt += 64) {
        #pragma unroll
        for (int i = 0; i < 8; i++) {
            int f4  = tid + i * 128;
            int row = f4 >> 4;
            int c   = f4 & 15;
            int k   = kt + c * 4;
            int r   = rowBase + row;
            float4 v = make_float4(0.f, 0.f, 0.f, 0.f);
            if (r < NN)
                v = *(const float4*)(g_agg1 + (size_t)r * F1 + k);
            v.x = fmaxf(v.x + sBias[k + 0], 0.f);
            v.y = fmaxf(v.y + sBias[k + 1], 0.f);
            v.z = fmaxf(v.z + sBias[k + 2], 0.f);
            v.w = fmaxf(v.w + sBias[k + 3], 0.f);
            sA[row][c * 4 + 0] = v.x;
            sA[row][c * 4 + 1] = v.y;
            sA[row][c * 4 + 2] = v.z;
            sA[row][c * 4 + 3] = v.w;
        }
        __syncthreads();

        #pragma unroll 16
        for (int kk = 0; kk < 64; kk++) {
            float a[4], b[5];
            #pragma unroll
            for (int j = 0; j < 4; j++) a[j] = sA[ty * 4 + j][kk];
            #pragma unroll
            for (int i = 0; i < 5; i++) b[i] = sW[(kt + kk) * F2 + tx * 5 + i];
            #pragma unroll
            for (int j = 0; j < 4; j++)
                #pragma unroll
                for (int i = 0; i < 5; i++)
                    acc[j][i] += a[j] * b[i];
        }
        __syncthreads();
    }

    #pragma unroll
    for (int j = 0; j < 4; j++) {
        int r = rowBase + ty * 4 + j;
        if (r >= NN) continue;
        #pragma unroll
        for (int i = 0; i < 5; i++)
            g_h2h[(size_t)r * F2 + tx * 5 + i] = __float2half_rn(acc[j][i]);
    }
}

// ---- gather layer 2 + bias + log_softmax fused: one warp per node ----
__global__ void k_gather2_lsm(const float* __restrict__ b2,
                              float* __restrict__ out) {
    int g = blockIdx.x * blockDim.x + threadIdx.x;
    int node = g >> 5;
    int lane = g & 31;
    if (node >= NN) return;

    bool act = lane < 10;
    float dd = g_dinv[node];
    float4 acc = make_float4(0.f, 0.f, 0.f, 0.f);
    if (act)
        acc_half4(acc, g_h2h + (size_t)node * F2 + lane * 4, dd * dd);

    int beg = g_off[node];
    int end = g_off[node + 1];
    for (int j = beg; j < end; j++) {
        int2 p = __ldg(g_csrp + j);
        if (act)
            acc_half4(acc, g_h2h + (size_t)p.x * F2 + lane * 4, __int_as_float(p.y));
    }

    if (act) {
        acc.x += b2[lane * 4 + 0];
        acc.y += b2[lane * 4 + 1];
        acc.z += b2[lane * 4 + 2];
        acc.w += b2[lane * 4 + 3];
    }

    float m = act ? fmaxf(fmaxf(acc.x, acc.y), fmaxf(acc.z, acc.w)) : -INFINITY;
    #pragma unroll
    for (int o = 16; o; o >>= 1) m = fmaxf(m, __shfl_xor_sync(0xFFFFFFFFu, m, o));
    float s = act ? (expf(acc.x - m) + expf(acc.y - m) +
                     expf(acc.z - m) + expf(acc.w - m)) : 0.f;
    #pragma unroll
    for (int o = 16; o; o >>= 1) s += __shfl_xor_sync(0xFFFFFFFFu, s, o);
    float l = m + logf(s);

    if (act) {
        float4 r = make_float4(acc.x - l, acc.y - l, acc.z - l, acc.w - l);
        *(float4*)(out + (size_t)node * F2 + lane * 4) = r;
    }
}

extern "C" void kernel_launch(void* const* d_in, const int* in_sizes, int n_in,
                              void* d_out, int out_size) {
    const float* x   = (const float*)d_in[0];
    const void*  ei  = d_in[1];
    const float* W1  = (const float*)d_in[2];
    const float* b1  = (const float*)d_in[3];
    const float* W2  = (const float*)d_in[4];
    const float* b2  = (const float*)d_in[5];
    float*       out = (float*)d_out;

    k_init    <<<(F0 * F1 + 255) / 256, 256>>>((const unsigned int*)ei, W1);
    k_convert <<<(2 * NE + 255) / 256, 256>>>(ei);
    k_scanA   <<<NB_SCAN, 256>>>();
    k_scanB   <<<1, 256>>>();
    k_scanC   <<<(NN + 255) / 256, 256>>>();
    k_fill    <<<(NE + 255) / 256, 256>>>();

    k_gemm1_mma<<<(NN + 127) / 128, 256>>>(x);
    k_gather1  <<<(int)(((long long)NN * 32 + 255) / 256), 256>>>();

    k_gemm2       <<<(NN + 63) / 64, 128>>>(W2, b1);
    k_gather2_lsm <<<(int)(((long long)NN * 32 + 255) / 256), 256>>>(b2, out);
}